// round 2
// baseline (speedup 1.0000x reference)
#include <cuda_runtime.h>
#include <cuda_bf16.h>

// Problem constants
#define Bc 8
#define Sq 2048
#define Ec 512
#define Hc 8
#define Dc 64
#define Mrows (Bc * Sq)   // 16384

// Scratch (no cudaMalloc allowed)
__device__ float g_Q[(size_t)Mrows * Ec];
__device__ float g_K[(size_t)Mrows * Ec];
__device__ float g_V[(size_t)Mrows * Ec];
__device__ float g_C[(size_t)Mrows * Ec];

// ---------------------------------------------------------------------------
// SGEMM: C = (A @ W + bias) * scale
// A [M,K] row-major, W [K,N] row-major, bias [N]
// 64x64 tile, Bk=16, 256 threads, 4x4 micro-tile
// ---------------------------------------------------------------------------
__global__ __launch_bounds__(256) void sgemm_bias(
    const float* __restrict__ A, const float* __restrict__ W,
    const float* __restrict__ bias, float* __restrict__ C,
    int M, int N, int K, float scale)
{
    __shared__ float As[16][65];   // [k][m]  (transposed A tile)
    __shared__ float Ws[16][65];   // [k][n]

    const int tid = threadIdx.x;
    const int tx = tid & 15, ty = tid >> 4;
    const int m0 = blockIdx.y * 64, n0 = blockIdx.x * 64;

    float acc[4][4] = {};

    for (int k0 = 0; k0 < K; k0 += 16) {
        {   // A tile: 64 rows x 16 k, one float4 per thread, store transposed
            int r  = tid >> 2;
            int c4 = (tid & 3) << 2;
            float4 v = *(const float4*)(A + (size_t)(m0 + r) * K + k0 + c4);
            As[c4 + 0][r] = v.x; As[c4 + 1][r] = v.y;
            As[c4 + 2][r] = v.z; As[c4 + 3][r] = v.w;
        }
        {   // W tile: 16 k x 64 n
            int r  = tid >> 4;
            int c4 = (tid & 15) << 2;
            float4 v = *(const float4*)(W + (size_t)(k0 + r) * N + n0 + c4);
            Ws[r][c4 + 0] = v.x; Ws[r][c4 + 1] = v.y;
            Ws[r][c4 + 2] = v.z; Ws[r][c4 + 3] = v.w;
        }
        __syncthreads();

        #pragma unroll
        for (int k = 0; k < 16; ++k) {
            float a[4], b[4];
            #pragma unroll
            for (int i = 0; i < 4; ++i) a[i] = As[k][(ty << 2) + i];
            #pragma unroll
            for (int j = 0; j < 4; ++j) b[j] = Ws[k][(tx << 2) + j];
            #pragma unroll
            for (int i = 0; i < 4; ++i)
                #pragma unroll
                for (int j = 0; j < 4; ++j)
                    acc[i][j] = fmaf(a[i], b[j], acc[i][j]);
        }
        __syncthreads();
    }

    #pragma unroll
    for (int i = 0; i < 4; ++i) {
        size_t m = (size_t)m0 + (ty << 2) + i;
        #pragma unroll
        for (int j = 0; j < 4; ++j) {
            int n = n0 + (tx << 2) + j;
            C[m * N + n] = (acc[i][j] + bias[n]) * scale;
        }
    }
}

// ---------------------------------------------------------------------------
// Flash attention: one CTA handles 64 query rows of one (b,h).
// Q pre-scaled by 1/sqrt(D). Streams 32 K/V tiles of 64 rows, online softmax.
// Smem rows padded to 65 floats (bank-conflict mitigation, scalar LDS).
// ---------------------------------------------------------------------------
#define FP 65

__global__ __launch_bounds__(256) void flash_attn(
    const float* __restrict__ Q, const float* __restrict__ K,
    const float* __restrict__ V, const int* __restrict__ mask,
    float* __restrict__ Ctx)
{
    extern __shared__ float sm[];
    float* Qs   = sm;                 // [64][FP]  (row-major [m][d])
    float* Ks   = sm + 64 * FP;       // [64][FP]  ([n][d])
    float* Vs   = sm + 2 * 64 * FP;   // [64][FP]  ([n][d])
    float* Ps   = sm + 3 * 64 * FP;   // [64][FP]  ([n][m], transposed P)
    float* mneg = sm + 4 * 64 * FP;   // [64]

    const int tid = threadIdx.x;
    const int tx = tid & 15, ty = tid >> 4;
    const int b = blockIdx.y >> 3, h = blockIdx.y & 7;
    const int m0 = blockIdx.x * 64;

    const float* Qb = Q + ((size_t)b * Sq + m0) * Ec + h * Dc;
    const float* Kb = K + (size_t)b * Sq * Ec + h * Dc;
    const float* Vb = V + (size_t)b * Sq * Ec + h * Dc;
    const int*   mb = mask + b * Sq;

    // Load Q tile once (coalesced; scalar smem stores due to odd row pitch)
    #pragma unroll
    for (int p = 0; p < 4; ++p) {
        int r  = p * 16 + (tid >> 4);
        int c4 = (tid & 15) << 2;
        float4 v = *(const float4*)(Qb + (size_t)r * Ec + c4);
        Qs[r * FP + c4 + 0] = v.x; Qs[r * FP + c4 + 1] = v.y;
        Qs[r * FP + c4 + 2] = v.z; Qs[r * FP + c4 + 3] = v.w;
    }

    float mi[4], li[4], o[4][4];
    #pragma unroll
    for (int i = 0; i < 4; ++i) {
        mi[i] = -1e30f; li[i] = 0.f;
        #pragma unroll
        for (int j = 0; j < 4; ++j) o[i][j] = 0.f;
    }

    for (int kt = 0; kt < Sq / 64; ++kt) {
        __syncthreads();   // previous iteration's reads of Ks/Vs/Ps done
        const int n0 = kt * 64;

        #pragma unroll
        for (int p = 0; p < 4; ++p) {
            int r  = p * 16 + (tid >> 4);
            int c4 = (tid & 15) << 2;
            float4 v = *(const float4*)(Kb + (size_t)(n0 + r) * Ec + c4);
            Ks[r * FP + c4 + 0] = v.x; Ks[r * FP + c4 + 1] = v.y;
            Ks[r * FP + c4 + 2] = v.z; Ks[r * FP + c4 + 3] = v.w;
            float4 w = *(const float4*)(Vb + (size_t)(n0 + r) * Ec + c4);
            Vs[r * FP + c4 + 0] = w.x; Vs[r * FP + c4 + 1] = w.y;
            Vs[r * FP + c4 + 2] = w.z; Vs[r * FP + c4 + 3] = w.w;
        }
        if (tid < 64) mneg[tid] = -1e9f * (float)mb[n0 + tid];
        __syncthreads();

        // S = Q K^T : rows (ty*4+i), cols (tx*4+j)
        float s[4][4] = {};
        #pragma unroll
        for (int k = 0; k < Dc; ++k) {
            float a[4], bb[4];
            #pragma unroll
            for (int i = 0; i < 4; ++i) a[i]  = Qs[((ty << 2) + i) * FP + k];
            #pragma unroll
            for (int j = 0; j < 4; ++j) bb[j] = Ks[((tx << 2) + j) * FP + k];
            #pragma unroll
            for (int i = 0; i < 4; ++i)
                #pragma unroll
                for (int j = 0; j < 4; ++j)
                    s[i][j] = fmaf(a[i], bb[j], s[i][j]);
        }
        #pragma unroll
        for (int i = 0; i < 4; ++i)
            #pragma unroll
            for (int j = 0; j < 4; ++j)
                s[i][j] += mneg[(tx << 2) + j];

        // Online softmax (row groups of 16 lanes: tx = lane & 15)
        #pragma unroll
        for (int i = 0; i < 4; ++i) {
            float rmax = fmaxf(fmaxf(s[i][0], s[i][1]), fmaxf(s[i][2], s[i][3]));
            rmax = fmaxf(rmax, __shfl_xor_sync(0xffffffffu, rmax, 1));
            rmax = fmaxf(rmax, __shfl_xor_sync(0xffffffffu, rmax, 2));
            rmax = fmaxf(rmax, __shfl_xor_sync(0xffffffffu, rmax, 4));
            rmax = fmaxf(rmax, __shfl_xor_sync(0xffffffffu, rmax, 8));
            float mnew  = fmaxf(mi[i], rmax);
            float alpha = __expf(mi[i] - mnew);
            float rsum = 0.f;
            #pragma unroll
            for (int j = 0; j < 4; ++j) {
                s[i][j] = __expf(s[i][j] - mnew);
                rsum += s[i][j];
            }
            rsum += __shfl_xor_sync(0xffffffffu, rsum, 1);
            rsum += __shfl_xor_sync(0xffffffffu, rsum, 2);
            rsum += __shfl_xor_sync(0xffffffffu, rsum, 4);
            rsum += __shfl_xor_sync(0xffffffffu, rsum, 8);
            li[i] = li[i] * alpha + rsum;
            mi[i] = mnew;
            #pragma unroll
            for (int j = 0; j < 4; ++j) o[i][j] *= alpha;
        }

        // Store P transposed: Ps[n][m]
        #pragma unroll
        for (int i = 0; i < 4; ++i)
            #pragma unroll
            for (int j = 0; j < 4; ++j)
                Ps[((tx << 2) + j) * FP + (ty << 2) + i] = s[i][j];
        __syncthreads();

        // O[m][d] += sum_n P[m][n] * V[n][d]
        #pragma unroll
        for (int n = 0; n < 64; ++n) {
            float a[4], bb[4];
            #pragma unroll
            for (int i = 0; i < 4; ++i) a[i]  = Ps[n * FP + (ty << 2) + i];
            #pragma unroll
            for (int j = 0; j < 4; ++j) bb[j] = Vs[n * FP + (tx << 2) + j];
            #pragma unroll
            for (int i = 0; i < 4; ++i)
                #pragma unroll
                for (int j = 0; j < 4; ++j)
                    o[i][j] = fmaf(a[i], bb[j], o[i][j]);
        }
    }

    // Epilogue: normalize, write context in (B,S,E) layout
    #pragma unroll
    for (int i = 0; i < 4; ++i) {
        float inv = 1.f / li[i];
        size_t m = (size_t)m0 + (ty << 2) + i;
        float4 v = make_float4(o[i][0] * inv, o[i][1] * inv,
                               o[i][2] * inv, o[i][3] * inv);
        *(float4*)(Ctx + ((size_t)b * Sq + m) * Ec + h * Dc + (tx << 2)) = v;
    }
}

// ---------------------------------------------------------------------------
// Host launcher
// ---------------------------------------------------------------------------
extern "C" void kernel_launch(void* const* d_in, const int* in_sizes, int n_in,
                              void* d_out, int out_size)
{
    const float* value = (const float*)d_in[0];
    const float* key   = (const float*)d_in[1];
    const float* query = (const float*)d_in[2];
    const int*   mask  = (const int*)d_in[3];
    const float* wq = (const float*)d_in[4];
    const float* bq = (const float*)d_in[5];
    const float* wk = (const float*)d_in[6];
    const float* bk = (const float*)d_in[7];
    const float* wv = (const float*)d_in[8];
    const float* bv = (const float*)d_in[9];
    const float* wo = (const float*)d_in[10];
    const float* bo = (const float*)d_in[11];
    float* out = (float*)d_out;

    float *Qp, *Kp, *Vp, *Cp;
    cudaGetSymbolAddress((void**)&Qp, g_Q);
    cudaGetSymbolAddress((void**)&Kp, g_K);
    cudaGetSymbolAddress((void**)&Vp, g_V);
    cudaGetSymbolAddress((void**)&Cp, g_C);

    const int smem_bytes = (4 * 64 * FP + 64) * (int)sizeof(float);   // 66816
    cudaFuncSetAttribute(flash_attn, cudaFuncAttributeMaxDynamicSharedMemorySize,
                         smem_bytes);

    dim3 gproj(Ec / 64, Mrows / 64);   // (8, 256)

    // Projections. Q gets 1/sqrt(D)=0.125 folded in.
    sgemm_bias<<<gproj, 256>>>(query, wq, bq, Qp, Mrows, Ec, Ec, 0.125f);
    sgemm_bias<<<gproj, 256>>>(key,   wk, bk, Kp, Mrows, Ec, Ec, 1.0f);
    sgemm_bias<<<gproj, 256>>>(value, wv, bv, Vp, Mrows, Ec, Ec, 1.0f);

    // Flash attention: grid (q-tiles, B*H)
    flash_attn<<<dim3(Sq / 64, Bc * Hc), 256, smem_bytes>>>(Qp, Kp, Vp, mask, Cp);

    // Output projection
    sgemm_bias<<<gproj, 256>>>(Cp, wo, bo, out, Mrows, Ec, Ec, 1.0f);
}

// round 4
// speedup vs baseline: 2.2686x; 2.2686x over previous
#include <cuda_runtime.h>
#include <cuda_bf16.h>
#include <cstdint>

// Problem constants
#define Bc 8
#define Sq 2048
#define Ec 512
#define Hc 8
#define Dc 64
#define Mrows (Bc * Sq)   // 16384

#define LOG2E 1.4426950408889634f

// Scratch (no cudaMalloc allowed)
__device__ float g_Q[(size_t)Mrows * Ec];
__device__ float g_K[(size_t)Mrows * Ec];
__device__ float g_V[(size_t)Mrows * Ec];
__device__ float g_C[(size_t)Mrows * Ec];

// ---------------------------------------------------------------------------
// helpers
// ---------------------------------------------------------------------------
__device__ __forceinline__ uint32_t f2t(float x) {
    uint32_t u;
    asm("cvt.rna.tf32.f32 %0, %1;" : "=r"(u) : "f"(x));
    return u;
}

__device__ __forceinline__ void mma_tf32(float c[4],
    uint32_t a0, uint32_t a1, uint32_t a2, uint32_t a3,
    uint32_t b0, uint32_t b1)
{
    asm volatile(
        "mma.sync.aligned.m16n8k8.row.col.f32.tf32.tf32.f32 "
        "{%0,%1,%2,%3}, {%4,%5,%6,%7}, {%8,%9}, {%0,%1,%2,%3};"
        : "+f"(c[0]), "+f"(c[1]), "+f"(c[2]), "+f"(c[3])
        : "r"(a0), "r"(a1), "r"(a2), "r"(a3), "r"(b0), "r"(b1));
}

// ---------------------------------------------------------------------------
// tf32 GEMM: C = (A @ W + bias) * scale
// A [M,K] row-major, W [K,N] row-major. CTA tile 128x64, Bk=32, 256 threads.
// 8 warps: 4(m) x 2(n), each warp 32x32 = 2 m16 x 4 n8 tiles.
// Smem pitches: As pitch 36 (A-frag reads: 4g+t bijective -> conflict-free),
//               Ws pitch 72 (B-frag reads: 8t+g bijective -> conflict-free).
// ---------------------------------------------------------------------------
__global__ __launch_bounds__(256) void gemm_tf32(
    const float* __restrict__ A, const float* __restrict__ W,
    const float* __restrict__ bias, float* __restrict__ C,
    int M, int N, int K, float scale)
{
    __shared__ uint32_t As[128][36];
    __shared__ uint32_t Ws[32][72];

    const int tid  = threadIdx.x;
    const int lane = tid & 31;
    const int w    = tid >> 5;
    const int wm   = w >> 1;        // 0..3
    const int wn   = w & 1;         // 0..1
    const int g    = lane >> 2;     // 0..7
    const int t    = lane & 3;      // 0..3
    const int m0   = blockIdx.y * 128;
    const int n0   = blockIdx.x * 64;

    float acc[2][4][4] = {};

    for (int k0 = 0; k0 < K; k0 += 32) {
        // A tile: 128 x 32
        #pragma unroll
        for (int p = 0; p < 4; ++p) {
            int i  = p * 256 + tid;
            int r  = i >> 3;
            int c4 = (i & 7) << 2;
            float4 v = *(const float4*)(A + (size_t)(m0 + r) * K + k0 + c4);
            uint4 u = make_uint4(f2t(v.x), f2t(v.y), f2t(v.z), f2t(v.w));
            *(uint4*)&As[r][c4] = u;
        }
        // W tile: 32 x 64
        #pragma unroll
        for (int p = 0; p < 2; ++p) {
            int i  = p * 256 + tid;
            int r  = i >> 4;
            int c4 = (i & 15) << 2;
            float4 v = *(const float4*)(W + (size_t)(k0 + r) * N + n0 + c4);
            uint4 u = make_uint4(f2t(v.x), f2t(v.y), f2t(v.z), f2t(v.w));
            *(uint4*)&Ws[r][c4] = u;
        }
        __syncthreads();

        #pragma unroll
        for (int k8 = 0; k8 < 4; ++k8) {
            uint32_t a[2][4];
            #pragma unroll
            for (int mt = 0; mt < 2; ++mt) {
                int m = wm * 32 + mt * 16;
                a[mt][0] = As[m + g    ][k8 * 8 + t];
                a[mt][1] = As[m + g + 8][k8 * 8 + t];
                a[mt][2] = As[m + g    ][k8 * 8 + t + 4];
                a[mt][3] = As[m + g + 8][k8 * 8 + t + 4];
            }
            #pragma unroll
            for (int nt = 0; nt < 4; ++nt) {
                uint32_t b0 = Ws[k8 * 8 + t    ][wn * 32 + nt * 8 + g];
                uint32_t b1 = Ws[k8 * 8 + t + 4][wn * 32 + nt * 8 + g];
                #pragma unroll
                for (int mt = 0; mt < 2; ++mt)
                    mma_tf32(acc[mt][nt], a[mt][0], a[mt][1], a[mt][2], a[mt][3], b0, b1);
            }
        }
        __syncthreads();
    }

    // Epilogue
    #pragma unroll
    for (int mt = 0; mt < 2; ++mt) {
        #pragma unroll
        for (int nt = 0; nt < 4; ++nt) {
            int m = m0 + wm * 32 + mt * 16 + g;
            int n = n0 + wn * 32 + nt * 8 + 2 * t;
            float b0v = bias[n], b1v = bias[n + 1];
            float2 r0 = make_float2((acc[mt][nt][0] + b0v) * scale,
                                    (acc[mt][nt][1] + b1v) * scale);
            float2 r1 = make_float2((acc[mt][nt][2] + b0v) * scale,
                                    (acc[mt][nt][3] + b1v) * scale);
            *(float2*)(C + (size_t)m * N + n)       = r0;
            *(float2*)(C + (size_t)(m + 8) * N + n) = r1;
        }
    }
}

// ---------------------------------------------------------------------------
// Flash attention with tf32 mma. One CTA = 64 q-rows of one (b,h).
// 128 threads = 4 warps, each warp owns 16 q-rows.
// Q pre-scaled by 0.125*log2(e); softmax via exp2.
// Smem: Qs (aliased as Ps after Q-frag preload) pitch 68, Ks pitch 68,
//       Vs pitch 72 — all fragment reads bank-conflict-free.
// ---------------------------------------------------------------------------
#define QP 68
#define VP 72

__global__ __launch_bounds__(128) void flash_attn_mma(
    const float* __restrict__ Q, const float* __restrict__ K,
    const float* __restrict__ V, const int* __restrict__ mask,
    float* __restrict__ Ctx)
{
    extern __shared__ uint32_t sm[];
    uint32_t* Qs = sm;                       // [64][QP]  (also Ps after preload)
    uint32_t* Ks = sm + 64 * QP;             // [64][QP]
    uint32_t* Vs = sm + 2 * 64 * QP;         // [64][VP]
    float* mneg  = (float*)(sm + 2 * 64 * QP + 64 * VP);  // [64]

    const int tid  = threadIdx.x;
    const int lane = tid & 31;
    const int w    = tid >> 5;      // warp id: q-rows [w*16, w*16+16)
    const int g    = lane >> 2;
    const int t    = lane & 3;
    const int b    = blockIdx.y >> 3, h = blockIdx.y & 7;
    const int m0   = blockIdx.x * 64;
    const int w16  = w * 16;

    const float* Qb = Q + ((size_t)b * Sq + m0) * Ec + h * Dc;
    const float* Kb = K + (size_t)b * Sq * Ec + h * Dc;
    const float* Vb = V + (size_t)b * Sq * Ec + h * Dc;
    const int*   mb = mask + b * Sq;

    // Load Q tile 64x64 -> smem (tf32)
    #pragma unroll
    for (int p = 0; p < 8; ++p) {
        int i  = p * 128 + tid;
        int r  = i >> 4;
        int c4 = (i & 15) << 2;
        float4 v = *(const float4*)(Qb + (size_t)r * Ec + c4);
        uint4 u = make_uint4(f2t(v.x), f2t(v.y), f2t(v.z), f2t(v.w));
        *(uint4*)&Qs[r * QP + c4] = u;
    }
    __syncthreads();

    // Preload Q A-fragments into registers (reused for all 32 kv tiles)
    uint32_t qf[8][4];
    #pragma unroll
    for (int k8 = 0; k8 < 8; ++k8) {
        qf[k8][0] = Qs[(w16 + g    ) * QP + k8 * 8 + t];
        qf[k8][1] = Qs[(w16 + g + 8) * QP + k8 * 8 + t];
        qf[k8][2] = Qs[(w16 + g    ) * QP + k8 * 8 + t + 4];
        qf[k8][3] = Qs[(w16 + g + 8) * QP + k8 * 8 + t + 4];
    }
    uint32_t* Ps = Qs;   // reuse buffer

    float o[8][4] = {};
    float mi0 = -1e30f, mi1 = -1e30f, li0 = 0.f, li1 = 0.f;

    for (int kt = 0; kt < Sq / 64; ++kt) {
        __syncthreads();   // all warps done reading Ks/Vs/Ps of prev iter
        const int n0 = kt * 64;

        // Load K,V tiles (64x64 each) -> smem tf32
        #pragma unroll
        for (int p = 0; p < 8; ++p) {
            int i  = p * 128 + tid;
            int r  = i >> 4;
            int c4 = (i & 15) << 2;
            float4 kv = *(const float4*)(Kb + (size_t)(n0 + r) * Ec + c4);
            *(uint4*)&Ks[r * QP + c4] =
                make_uint4(f2t(kv.x), f2t(kv.y), f2t(kv.z), f2t(kv.w));
            float4 vv = *(const float4*)(Vb + (size_t)(n0 + r) * Ec + c4);
            *(uint4*)&Vs[r * VP + c4] =
                make_uint4(f2t(vv.x), f2t(vv.y), f2t(vv.z), f2t(vv.w));
        }
        if (tid < 64) mneg[tid] = (-1e9f * LOG2E) * (float)mb[n0 + tid];
        __syncthreads();

        // ---- S = Q K^T (scaled-by-log2e domain), 16x64 per warp ----
        float s[8][4] = {};
        #pragma unroll
        for (int k8 = 0; k8 < 8; ++k8) {
            #pragma unroll
            for (int nt = 0; nt < 8; ++nt) {
                uint32_t b0 = Ks[(nt * 8 + g) * QP + k8 * 8 + t];
                uint32_t b1 = Ks[(nt * 8 + g) * QP + k8 * 8 + t + 4];
                mma_tf32(s[nt], qf[k8][0], qf[k8][1], qf[k8][2], qf[k8][3], b0, b1);
            }
        }
        // mask add
        #pragma unroll
        for (int nt = 0; nt < 8; ++nt) {
            float2 mv = *(float2*)&mneg[nt * 8 + 2 * t];
            s[nt][0] += mv.x; s[nt][1] += mv.y;
            s[nt][2] += mv.x; s[nt][3] += mv.y;
        }

        // ---- online softmax (rows g and g+8; 4 threads per row) ----
        float mx0 = -1e30f, mx1 = -1e30f;
        #pragma unroll
        for (int nt = 0; nt < 8; ++nt) {
            mx0 = fmaxf(mx0, fmaxf(s[nt][0], s[nt][1]));
            mx1 = fmaxf(mx1, fmaxf(s[nt][2], s[nt][3]));
        }
        mx0 = fmaxf(mx0, __shfl_xor_sync(0xffffffffu, mx0, 1));
        mx0 = fmaxf(mx0, __shfl_xor_sync(0xffffffffu, mx0, 2));
        mx1 = fmaxf(mx1, __shfl_xor_sync(0xffffffffu, mx1, 1));
        mx1 = fmaxf(mx1, __shfl_xor_sync(0xffffffffu, mx1, 2));

        float mn0 = fmaxf(mi0, mx0), mn1 = fmaxf(mi1, mx1);
        float al0 = exp2f(mi0 - mn0), al1 = exp2f(mi1 - mn1);
        float sum0 = 0.f, sum1 = 0.f;
        #pragma unroll
        for (int nt = 0; nt < 8; ++nt) {
            s[nt][0] = exp2f(s[nt][0] - mn0);
            s[nt][1] = exp2f(s[nt][1] - mn0);
            s[nt][2] = exp2f(s[nt][2] - mn1);
            s[nt][3] = exp2f(s[nt][3] - mn1);
            sum0 += s[nt][0] + s[nt][1];
            sum1 += s[nt][2] + s[nt][3];
        }
        sum0 += __shfl_xor_sync(0xffffffffu, sum0, 1);
        sum0 += __shfl_xor_sync(0xffffffffu, sum0, 2);
        sum1 += __shfl_xor_sync(0xffffffffu, sum1, 1);
        sum1 += __shfl_xor_sync(0xffffffffu, sum1, 2);
        li0 = li0 * al0 + sum0;  mi0 = mn0;
        li1 = li1 * al1 + sum1;  mi1 = mn1;
        #pragma unroll
        for (int dt = 0; dt < 8; ++dt) {
            o[dt][0] *= al0; o[dt][1] *= al0;
            o[dt][2] *= al1; o[dt][3] *= al1;
        }

        // ---- store P (tf32) into Ps; each warp owns its own 16 rows ----
        #pragma unroll
        for (int nt = 0; nt < 8; ++nt) {
            *(uint2*)&Ps[(w16 + g    ) * QP + nt * 8 + 2 * t] =
                make_uint2(f2t(s[nt][0]), f2t(s[nt][1]));
            *(uint2*)&Ps[(w16 + g + 8) * QP + nt * 8 + 2 * t] =
                make_uint2(f2t(s[nt][2]), f2t(s[nt][3]));
        }
        __syncwarp();

        // ---- O += P @ V ----
        #pragma unroll
        for (int k8 = 0; k8 < 8; ++k8) {
            uint32_t a0 = Ps[(w16 + g    ) * QP + k8 * 8 + t];
            uint32_t a1 = Ps[(w16 + g + 8) * QP + k8 * 8 + t];
            uint32_t a2 = Ps[(w16 + g    ) * QP + k8 * 8 + t + 4];
            uint32_t a3 = Ps[(w16 + g + 8) * QP + k8 * 8 + t + 4];
            #pragma unroll
            for (int dt = 0; dt < 8; ++dt) {
                uint32_t b0 = Vs[(k8 * 8 + t    ) * VP + dt * 8 + g];
                uint32_t b1 = Vs[(k8 * 8 + t + 4) * VP + dt * 8 + g];
                mma_tf32(o[dt], a0, a1, a2, a3, b0, b1);
            }
        }
    }

    // Epilogue: normalize, write context (B,S,E) layout
    float inv0 = 1.f / li0, inv1 = 1.f / li1;
    float* Cb = Ctx + ((size_t)b * Sq + m0 + w16) * Ec + h * Dc;
    #pragma unroll
    for (int dt = 0; dt < 8; ++dt) {
        int n = dt * 8 + 2 * t;
        *(float2*)(Cb + (size_t)g * Ec + n) =
            make_float2(o[dt][0] * inv0, o[dt][1] * inv0);
        *(float2*)(Cb + (size_t)(g + 8) * Ec + n) =
            make_float2(o[dt][2] * inv1, o[dt][3] * inv1);
    }
}

// ---------------------------------------------------------------------------
// Host launcher
// ---------------------------------------------------------------------------
extern "C" void kernel_launch(void* const* d_in, const int* in_sizes, int n_in,
                              void* d_out, int out_size)
{
    const float* value = (const float*)d_in[0];
    const float* key   = (const float*)d_in[1];
    const float* query = (const float*)d_in[2];
    const int*   mask  = (const int*)d_in[3];
    const float* wq = (const float*)d_in[4];
    const float* bq = (const float*)d_in[5];
    const float* wk = (const float*)d_in[6];
    const float* bk = (const float*)d_in[7];
    const float* wv = (const float*)d_in[8];
    const float* bv = (const float*)d_in[9];
    const float* wo = (const float*)d_in[10];
    const float* bo = (const float*)d_in[11];
    float* out = (float*)d_out;

    float *Qp, *Kp, *Vp, *Cp;
    cudaGetSymbolAddress((void**)&Qp, g_Q);
    cudaGetSymbolAddress((void**)&Kp, g_K);
    cudaGetSymbolAddress((void**)&Vp, g_V);
    cudaGetSymbolAddress((void**)&Cp, g_C);

    const int fa_smem = (2 * 64 * QP + 64 * VP + 64) * (int)sizeof(uint32_t);  // 53504
    static int attr_set = 0;
    cudaFuncSetAttribute(flash_attn_mma, cudaFuncAttributeMaxDynamicSharedMemorySize,
                         fa_smem);
    (void)attr_set;

    dim3 gproj(Ec / 64, Mrows / 128);   // (8, 128)

    // Projections. Q gets 1/sqrt(D)*log2(e) folded in (softmax uses exp2).
    gemm_tf32<<<gproj, 256>>>(query, wq, bq, Qp, Mrows, Ec, Ec, 0.125f * LOG2E);
    gemm_tf32<<<gproj, 256>>>(key,   wk, bk, Kp, Mrows, Ec, Ec, 1.0f);
    gemm_tf32<<<gproj, 256>>>(value, wv, bv, Vp, Mrows, Ec, Ec, 1.0f);

    // Flash attention: grid (q-tiles, B*H)
    flash_attn_mma<<<dim3(Sq / 64, Bc * Hc), 128, fa_smem>>>(Qp, Kp, Vp, mask, Cp);

    // Output projection
    gemm_tf32<<<gproj, 256>>>(Cp, wo, bo, out, Mrows, Ec, Ec, 1.0f);
}

// round 11
// speedup vs baseline: 4.0012x; 1.7637x over previous
#include <cuda_runtime.h>
#include <cuda_bf16.h>
#include <cstdint>

// Problem constants
#define Bc 8
#define Sq 2048
#define Ec 512
#define Hc 8
#define Dc 64
#define Mrows (Bc * Sq)   // 16384

#define LOG2E 1.4426950408889634f

// Scratch (no cudaMalloc allowed)
__device__ float g_Q[(size_t)Mrows * Ec];
__device__ float g_K[(size_t)Mrows * Ec];
__device__ float g_V[(size_t)Mrows * Ec];
__device__ float g_C[(size_t)Mrows * Ec];
__device__ float g_T[(size_t)Mrows * Ec];    // tf32-rounded A operand
__device__ float g_WT[Ec * Ec];              // tf32-rounded W operand

// ---------------------------------------------------------------------------
// helpers
// ---------------------------------------------------------------------------
__device__ __forceinline__ uint32_t f2t(float x) {
    uint32_t u;
    asm("cvt.rna.tf32.f32 %0, %1;" : "=r"(u) : "f"(x));
    return u;
}

__device__ __forceinline__ void mma_tf32(float c[4],
    uint32_t a0, uint32_t a1, uint32_t a2, uint32_t a3,
    uint32_t b0, uint32_t b1)
{
    asm volatile(
        "mma.sync.aligned.m16n8k8.row.col.f32.tf32.tf32.f32 "
        "{%0,%1,%2,%3}, {%4,%5,%6,%7}, {%8,%9}, {%0,%1,%2,%3};"
        : "+f"(c[0]), "+f"(c[1]), "+f"(c[2]), "+f"(c[3])
        : "r"(a0), "r"(a1), "r"(a2), "r"(a3), "r"(b0), "r"(b1));
}

__device__ __forceinline__ uint32_t s2u(const void* p) {
    uint32_t a;
    asm("{ .reg .u64 t; cvta.to.shared.u64 t, %1; cvt.u32.u64 %0, t; }"
        : "=r"(a) : "l"(p));
    return a;
}

__device__ __forceinline__ void cpasync16(uint32_t dst, const void* src) {
    asm volatile("cp.async.cg.shared.global [%0], [%1], 16;" :: "r"(dst), "l"(src));
}
#define CP_COMMIT() asm volatile("cp.async.commit_group;" ::: "memory")
#define CP_WAIT(n)  asm volatile("cp.async.wait_group %0;" :: "n"(n) : "memory")

// ---------------------------------------------------------------------------
// elementwise tf32 rounding (x4 vectorized)
// ---------------------------------------------------------------------------
__global__ __launch_bounds__(256) void conv_tf32(
    const float* __restrict__ x, float* __restrict__ y, int n4)
{
    int i = blockIdx.x * 256 + threadIdx.x;
    if (i >= n4) return;
    float4 v = ((const float4*)x)[i];
    uint4 u = make_uint4(f2t(v.x), f2t(v.y), f2t(v.z), f2t(v.w));
    ((uint4*)y)[i] = u;
}

// ---------------------------------------------------------------------------
// tf32 GEMM v2: C = (A @ W + bias) * scale   [optionally tf32-round output]
// A [16384,512], W [512,512] row-major, both pre-rounded to tf32.
// CTA tile 128x128, Bk=32, 16 stages, double-buffered cp.async.
// 8 warps = 2(m) x 4(n); warp tile 64x32 = 4 m16 x 4 n8.
// Smem pitches: A 36 words (bank 4g+t, conflict-free; 144B rows, 16B-aligned),
//               W 136 words (bank 8t+g, conflict-free; 544B rows, 16B-aligned).
// ---------------------------------------------------------------------------
#define APITCH 36
#define BPITCH 136
#define ASTG (128 * APITCH * 4)     // 18432 B
#define BSTG (32 * BPITCH * 4)      // 17408 B
#define GSTG (ASTG + BSTG)          // 35840 B
#define GSMEM (2 * GSTG)            // 71680 B

__global__ __launch_bounds__(256) void gemm_tf32_v2(
    const float* __restrict__ A, const float* __restrict__ W,
    const float* __restrict__ bias, float* __restrict__ C,
    float scale, int round_out)
{
    extern __shared__ __align__(16) uint8_t smem[];
    const uint32_t sb = s2u(smem);

    const int tid  = threadIdx.x;
    const int lane = tid & 31;
    const int w    = tid >> 5;
    const int wm   = w >> 2;        // 0..1
    const int wn   = w & 3;         // 0..3
    const int g    = lane >> 2;     // 0..7
    const int t    = lane & 3;      // 0..3
    const int m0   = blockIdx.y * 128;
    const int n0   = blockIdx.x * 128;

    const char* Ab = (const char*)A + (size_t)m0 * Ec * 4;
    const char* Wb = (const char*)W + (size_t)n0 * 4;

    auto fill = [&](int s) {
        uint32_t base = sb + (uint32_t)(s & 1) * GSTG;
        // A: 128 rows x 128B = 1024 chunks -> 4/thread
        #pragma unroll
        for (int q = 0; q < 4; ++q) {
            int i = q * 256 + tid;
            int r = i >> 3, c = i & 7;
            cpasync16(base + (uint32_t)(r * (APITCH * 4) + c * 16),
                      Ab + (size_t)r * (Ec * 4) + s * 128 + c * 16);
        }
        // W: 32 rows x 512B = 1024 chunks -> 4/thread
        #pragma unroll
        for (int q = 0; q < 4; ++q) {
            int i = q * 256 + tid;
            int r = i >> 5, c = i & 31;
            cpasync16(base + ASTG + (uint32_t)(r * (BPITCH * 4) + c * 16),
                      Wb + (size_t)(s * 32 + r) * (Ec * 4) + c * 16);
        }
        CP_COMMIT();
    };

    float acc[4][4][4] = {};
    fill(0);

    const uint32_t* As;
    const uint32_t* Ws;

    for (int s = 0; s < 16; ++s) {
        if (s < 15) {
            fill(s + 1);
            CP_WAIT(1);
        } else {
            CP_WAIT(0);
        }
        __syncthreads();

        const uint8_t* buf = smem + (s & 1) * GSTG;
        As = (const uint32_t*)buf;
        Ws = (const uint32_t*)(buf + ASTG);

        #pragma unroll
        for (int k8 = 0; k8 < 4; ++k8) {
            uint32_t a[4][4];
            #pragma unroll
            for (int mt = 0; mt < 4; ++mt) {
                int m = wm * 64 + mt * 16;
                a[mt][0] = As[(m + g    ) * APITCH + k8 * 8 + t];
                a[mt][1] = As[(m + g + 8) * APITCH + k8 * 8 + t];
                a[mt][2] = As[(m + g    ) * APITCH + k8 * 8 + t + 4];
                a[mt][3] = As[(m + g + 8) * APITCH + k8 * 8 + t + 4];
            }
            #pragma unroll
            for (int nt = 0; nt < 4; ++nt) {
                uint32_t b0 = Ws[(k8 * 8 + t    ) * BPITCH + wn * 32 + nt * 8 + g];
                uint32_t b1 = Ws[(k8 * 8 + t + 4) * BPITCH + wn * 32 + nt * 8 + g];
                #pragma unroll
                for (int mt = 0; mt < 4; ++mt)
                    mma_tf32(acc[mt][nt], a[mt][0], a[mt][1], a[mt][2], a[mt][3], b0, b1);
            }
        }
        __syncthreads();
    }

    // Epilogue
    #pragma unroll
    for (int mt = 0; mt < 4; ++mt) {
        #pragma unroll
        for (int nt = 0; nt < 4; ++nt) {
            int m = m0 + wm * 64 + mt * 16 + g;
            int n = n0 + wn * 32 + nt * 8 + 2 * t;
            float b0v = bias[n], b1v = bias[n + 1];
            float v00 = (acc[mt][nt][0] + b0v) * scale;
            float v01 = (acc[mt][nt][1] + b1v) * scale;
            float v10 = (acc[mt][nt][2] + b0v) * scale;
            float v11 = (acc[mt][nt][3] + b1v) * scale;
            if (round_out) {
                v00 = __uint_as_float(f2t(v00));
                v01 = __uint_as_float(f2t(v01));
                v10 = __uint_as_float(f2t(v10));
                v11 = __uint_as_float(f2t(v11));
            }
            *(float2*)(C + (size_t)m * Ec + n)       = make_float2(v00, v01);
            *(float2*)(C + (size_t)(m + 8) * Ec + n) = make_float2(v10, v11);
        }
    }
}

// ---------------------------------------------------------------------------
// Flash attention with tf32 mma. One CTA = 64 q-rows of one (b,h).
// Q/K/V already tf32-rounded by projection epilogue -> loads are cp.async.
// Layout, mma structure, softmax identical to the passing round-3 kernel.
// ---------------------------------------------------------------------------
#define QP 68
#define VP 72

__global__ __launch_bounds__(128) void flash_attn_mma(
    const float* __restrict__ Q, const float* __restrict__ K,
    const float* __restrict__ V, const int* __restrict__ mask,
    float* __restrict__ Ctx)
{
    extern __shared__ uint32_t sm[];
    uint32_t* Qs = sm;                       // [64][QP]  (also Ps after preload)
    uint32_t* Ks = sm + 64 * QP;             // [64][QP]
    uint32_t* Vs = sm + 2 * 64 * QP;         // [64][VP]
    float* mneg  = (float*)(sm + 2 * 64 * QP + 64 * VP);  // [64]

    const uint32_t sbase = s2u(sm);
    const uint32_t qsb = sbase;
    const uint32_t ksb = sbase + 64 * QP * 4;
    const uint32_t vsb = sbase + 2 * 64 * QP * 4;

    const int tid  = threadIdx.x;
    const int lane = tid & 31;
    const int w    = tid >> 5;
    const int g    = lane >> 2;
    const int t    = lane & 3;
    const int b    = blockIdx.y >> 3, h = blockIdx.y & 7;
    const int m0   = blockIdx.x * 64;
    const int w16  = w * 16;

    const char* Qb = (const char*)(Q + ((size_t)b * Sq + m0) * Ec + h * Dc);
    const char* Kb = (const char*)(K + (size_t)b * Sq * Ec + h * Dc);
    const char* Vb = (const char*)(V + (size_t)b * Sq * Ec + h * Dc);
    const int*  mb = mask + b * Sq;

    // Load Q tile 64x64 via cp.async (already tf32 bit patterns)
    #pragma unroll
    for (int p = 0; p < 8; ++p) {
        int i = p * 128 + tid;
        int r = i >> 4, c = i & 15;
        cpasync16(qsb + (uint32_t)(r * (QP * 4) + c * 16),
                  Qb + (size_t)r * (Ec * 4) + c * 16);
    }
    CP_COMMIT();
    CP_WAIT(0);
    __syncthreads();

    // Preload Q A-fragments into registers (reused for all 32 kv tiles)
    uint32_t qf[8][4];
    #pragma unroll
    for (int k8 = 0; k8 < 8; ++k8) {
        qf[k8][0] = Qs[(w16 + g    ) * QP + k8 * 8 + t];
        qf[k8][1] = Qs[(w16 + g + 8) * QP + k8 * 8 + t];
        qf[k8][2] = Qs[(w16 + g    ) * QP + k8 * 8 + t + 4];
        qf[k8][3] = Qs[(w16 + g + 8) * QP + k8 * 8 + t + 4];
    }
    uint32_t* Ps = Qs;   // reuse buffer

    float o[8][4] = {};
    float mi0 = -1e30f, mi1 = -1e30f, li0 = 0.f, li1 = 0.f;

    for (int kt = 0; kt < Sq / 64; ++kt) {
        __syncthreads();   // all warps done reading Ks/Vs/Ps of prev iter
        const int n0 = kt * 64;

        // K,V tiles via cp.async (no cvt, no register round-trip)
        #pragma unroll
        for (int p = 0; p < 8; ++p) {
            int i = p * 128 + tid;
            int r = i >> 4, c = i & 15;
            size_t goff = (size_t)(n0 + r) * (Ec * 4) + c * 16;
            cpasync16(ksb + (uint32_t)(r * (QP * 4) + c * 16), Kb + goff);
            cpasync16(vsb + (uint32_t)(r * (VP * 4) + c * 16), Vb + goff);
        }
        CP_COMMIT();
        CP_WAIT(0);
        if (tid < 64) mneg[tid] = (-1e9f * LOG2E) * (float)mb[n0 + tid];
        __syncthreads();

        // ---- S = Q K^T (log2e domain), 16x64 per warp ----
        float s[8][4] = {};
        #pragma unroll
        for (int k8 = 0; k8 < 8; ++k8) {
            #pragma unroll
            for (int nt = 0; nt < 8; ++nt) {
                uint32_t b0 = Ks[(nt * 8 + g) * QP + k8 * 8 + t];
                uint32_t b1 = Ks[(nt * 8 + g) * QP + k8 * 8 + t + 4];
                mma_tf32(s[nt], qf[k8][0], qf[k8][1], qf[k8][2], qf[k8][3], b0, b1);
            }
        }
        #pragma unroll
        for (int nt = 0; nt < 8; ++nt) {
            float2 mv = *(float2*)&mneg[nt * 8 + 2 * t];
            s[nt][0] += mv.x; s[nt][1] += mv.y;
            s[nt][2] += mv.x; s[nt][3] += mv.y;
        }

        // ---- online softmax (rows g and g+8; 4 threads per row) ----
        float mx0 = -1e30f, mx1 = -1e30f;
        #pragma unroll
        for (int nt = 0; nt < 8; ++nt) {
            mx0 = fmaxf(mx0, fmaxf(s[nt][0], s[nt][1]));
            mx1 = fmaxf(mx1, fmaxf(s[nt][2], s[nt][3]));
        }
        mx0 = fmaxf(mx0, __shfl_xor_sync(0xffffffffu, mx0, 1));
        mx0 = fmaxf(mx0, __shfl_xor_sync(0xffffffffu, mx0, 2));
        mx1 = fmaxf(mx1, __shfl_xor_sync(0xffffffffu, mx1, 1));
        mx1 = fmaxf(mx1, __shfl_xor_sync(0xffffffffu, mx1, 2));

        float mn0 = fmaxf(mi0, mx0), mn1 = fmaxf(mi1, mx1);
        float al0 = exp2f(mi0 - mn0), al1 = exp2f(mi1 - mn1);
        float sum0 = 0.f, sum1 = 0.f;
        #pragma unroll
        for (int nt = 0; nt < 8; ++nt) {
            s[nt][0] = exp2f(s[nt][0] - mn0);
            s[nt][1] = exp2f(s[nt][1] - mn0);
            s[nt][2] = exp2f(s[nt][2] - mn1);
            s[nt][3] = exp2f(s[nt][3] - mn1);
            sum0 += s[nt][0] + s[nt][1];
            sum1 += s[nt][2] + s[nt][3];
        }
        sum0 += __shfl_xor_sync(0xffffffffu, sum0, 1);
        sum0 += __shfl_xor_sync(0xffffffffu, sum0, 2);
        sum1 += __shfl_xor_sync(0xffffffffu, sum1, 1);
        sum1 += __shfl_xor_sync(0xffffffffu, sum1, 2);
        li0 = li0 * al0 + sum0;  mi0 = mn0;
        li1 = li1 * al1 + sum1;  mi1 = mn1;
        #pragma unroll
        for (int dt = 0; dt < 8; ++dt) {
            o[dt][0] *= al0; o[dt][1] *= al0;
            o[dt][2] *= al1; o[dt][3] *= al1;
        }

        // ---- store P (tf32) into Ps; each warp owns its own 16 rows ----
        #pragma unroll
        for (int nt = 0; nt < 8; ++nt) {
            *(uint2*)&Ps[(w16 + g    ) * QP + nt * 8 + 2 * t] =
                make_uint2(f2t(s[nt][0]), f2t(s[nt][1]));
            *(uint2*)&Ps[(w16 + g + 8) * QP + nt * 8 + 2 * t] =
                make_uint2(f2t(s[nt][2]), f2t(s[nt][3]));
        }
        __syncwarp();

        // ---- O += P @ V ----
        #pragma unroll
        for (int k8 = 0; k8 < 8; ++k8) {
            uint32_t a0 = Ps[(w16 + g    ) * QP + k8 * 8 + t];
            uint32_t a1 = Ps[(w16 + g + 8) * QP + k8 * 8 + t];
            uint32_t a2 = Ps[(w16 + g    ) * QP + k8 * 8 + t + 4];
            uint32_t a3 = Ps[(w16 + g + 8) * QP + k8 * 8 + t + 4];
            #pragma unroll
            for (int dt = 0; dt < 8; ++dt) {
                uint32_t b0 = Vs[(k8 * 8 + t    ) * VP + dt * 8 + g];
                uint32_t b1 = Vs[(k8 * 8 + t + 4) * VP + dt * 8 + g];
                mma_tf32(o[dt], a0, a1, a2, a3, b0, b1);
            }
        }
    }

    // Epilogue: normalize, write context (B,S,E) layout
    float inv0 = 1.f / li0, inv1 = 1.f / li1;
    float* Cb = Ctx + ((size_t)b * Sq + m0 + w16) * Ec + h * Dc;
    #pragma unroll
    for (int dt = 0; dt < 8; ++dt) {
        int n = dt * 8 + 2 * t;
        *(float2*)(Cb + (size_t)g * Ec + n) =
            make_float2(o[dt][0] * inv0, o[dt][1] * inv0);
        *(float2*)(Cb + (size_t)(g + 8) * Ec + n) =
            make_float2(o[dt][2] * inv1, o[dt][3] * inv1);
    }
}

// ---------------------------------------------------------------------------
// Host launcher
// ---------------------------------------------------------------------------
extern "C" void kernel_launch(void* const* d_in, const int* in_sizes, int n_in,
                              void* d_out, int out_size)
{
    const float* value = (const float*)d_in[0];
    const float* key   = (const float*)d_in[1];
    const float* query = (const float*)d_in[2];
    const int*   mask  = (const int*)d_in[3];
    const float* wq = (const float*)d_in[4];
    const float* bq = (const float*)d_in[5];
    const float* wk = (const float*)d_in[6];
    const float* bk = (const float*)d_in[7];
    const float* wv = (const float*)d_in[8];
    const float* bv = (const float*)d_in[9];
    const float* wo = (const float*)d_in[10];
    const float* bo = (const float*)d_in[11];
    float* out = (float*)d_out;

    float *Qp, *Kp, *Vp, *Cp, *Tp, *WTp;
    cudaGetSymbolAddress((void**)&Qp, g_Q);
    cudaGetSymbolAddress((void**)&Kp, g_K);
    cudaGetSymbolAddress((void**)&Vp, g_V);
    cudaGetSymbolAddress((void**)&Cp, g_C);
    cudaGetSymbolAddress((void**)&Tp, g_T);
    cudaGetSymbolAddress((void**)&WTp, g_WT);

    const int fa_smem = (2 * 64 * QP + 64 * VP + 64) * (int)sizeof(uint32_t);  // 53504
    cudaFuncSetAttribute(flash_attn_mma, cudaFuncAttributeMaxDynamicSharedMemorySize,
                         fa_smem);
    cudaFuncSetAttribute(gemm_tf32_v2, cudaFuncAttributeMaxDynamicSharedMemorySize,
                         GSMEM);

    const int n4A = Mrows * Ec / 4;     // 2,097,152
    const int n4W = Ec * Ec / 4;        // 65,536
    dim3 ggemm(Ec / 128, Mrows / 128);  // (4, 128)

    // --- Q projection: scale folds 1/sqrt(D)*log2(e); output tf32-rounded ---
    conv_tf32<<<n4A / 256, 256>>>(query, Tp, n4A);
    conv_tf32<<<n4W / 256, 256>>>(wq, WTp, n4W);
    gemm_tf32_v2<<<ggemm, 256, GSMEM>>>(Tp, WTp, bq, Qp, 0.125f * LOG2E, 1);

    // --- K projection ---
    conv_tf32<<<n4A / 256, 256>>>(key, Tp, n4A);
    conv_tf32<<<n4W / 256, 256>>>(wk, WTp, n4W);
    gemm_tf32_v2<<<ggemm, 256, GSMEM>>>(Tp, WTp, bk, Kp, 1.0f, 1);

    // --- V projection ---
    conv_tf32<<<n4A / 256, 256>>>(value, Tp, n4A);
    conv_tf32<<<n4W / 256, 256>>>(wv, WTp, n4W);
    gemm_tf32_v2<<<ggemm, 256, GSMEM>>>(Tp, WTp, bv, Vp, 1.0f, 1);

    // --- attention ---
    flash_attn_mma<<<dim3(Sq / 64, Bc * Hc), 128, fa_smem>>>(Qp, Kp, Vp, mask, Cp);

    // --- output projection (fp32 output, no rounding) ---
    conv_tf32<<<n4A / 256, 256>>>(Cp, Tp, n4A);
    conv_tf32<<<n4W / 256, 256>>>(wo, WTp, n4W);
    gemm_tf32_v2<<<ggemm, 256, GSMEM>>>(Tp, WTp, bo, out, 1.0f, 0);
}